// round 6
// baseline (speedup 1.0000x reference)
#include <cuda_runtime.h>
#include <cuda_bf16.h>
#include <math.h>
#include <stdint.h>

// Problem dims
#define TT   512
#define BB   64
#define II   1024
#define HH   1024
#define N4H  4096
#define MTOT (TT*BB)        // 32768

// Step tiling
#define NCTA    128
#define NPC     32          // gate-output columns (p) per CTA
#define KCHUNK  64
#define NCHUNK  (HH/KCHUNK) // 16

// ---------------------------------------------------------------------------
// Device scratch (allocation-free)
// ---------------------------------------------------------------------------
__device__ float g_xp[(size_t)MTOT * N4H];         // input projections + bias, p-ordered
__device__ float g_c[BB * HH];                     // cell state
__device__ __nv_bfloat16 g_whi[(size_t)N4H * HH];  // Wh hi (p-ordered rows)
__device__ __nv_bfloat16 g_wlo[(size_t)N4H * HH];  // Wh lo
__device__ __nv_bfloat16 g_hhi[2][BB * HH];        // h hi ping-pong
__device__ __nv_bfloat16 g_hlo[2][BB * HH];        // h lo
__device__ __nv_bfloat16 g_xhi[(size_t)MTOT * II]; // X hi
__device__ __nv_bfloat16 g_xlo[(size_t)MTOT * II]; // X lo
__device__ __nv_bfloat16 g_wihi[(size_t)N4H * II]; // Wi hi (p-ordered rows)
__device__ __nv_bfloat16 g_wilo[(size_t)N4H * II]; // Wi lo
__device__ float g_bp[N4H];                        // bias, p-ordered
__device__ unsigned g_cnt[8];                      // producer-group counters

// ---------------------------------------------------------------------------
// Helpers
// ---------------------------------------------------------------------------
__device__ __forceinline__ uint32_t smem_u32(const void* p) {
    uint32_t a;
    asm("{ .reg .u64 t; cvta.to.shared.u64 t, %1; cvt.u32.u64 %0, t; }" : "=r"(a) : "l"(p));
    return a;
}
__device__ __forceinline__ void cp_async16(uint32_t smem_addr, const void* gptr) {
    asm volatile("cp.async.cg.shared.global [%0], [%1], 16;" :: "r"(smem_addr), "l"(gptr));
}
#define CP_COMMIT() asm volatile("cp.async.commit_group;" ::: "memory")

__device__ __forceinline__ void ldsm4(uint32_t* r, uint32_t addr) {
    asm volatile("ldmatrix.sync.aligned.m8n8.x4.shared.b16 {%0,%1,%2,%3}, [%4];"
                 : "=r"(r[0]), "=r"(r[1]), "=r"(r[2]), "=r"(r[3]) : "r"(addr));
}
__device__ __forceinline__ void ldsm2(uint32_t* r, uint32_t addr) {
    asm volatile("ldmatrix.sync.aligned.m8n8.x2.shared.b16 {%0,%1}, [%2];"
                 : "=r"(r[0]), "=r"(r[1]) : "r"(addr));
}
__device__ __forceinline__ void mma_bf16(float* d, const uint32_t* a, uint32_t b0, uint32_t b1) {
    asm volatile("mma.sync.aligned.m16n8k16.row.col.f32.bf16.bf16.f32 "
                 "{%0,%1,%2,%3}, {%4,%5,%6,%7}, {%8,%9}, {%0,%1,%2,%3};"
                 : "+f"(d[0]), "+f"(d[1]), "+f"(d[2]), "+f"(d[3])
                 : "r"(a[0]), "r"(a[1]), "r"(a[2]), "r"(a[3]), "r"(b0), "r"(b1));
}
__device__ __forceinline__ float sigmoidf_(float x) { return 1.f / (1.f + expf(-x)); }
#define SWZ(row, c16) ((uint32_t)((row) * 128 + (((c16) ^ ((row) & 7)) << 4)))

__device__ __forceinline__ uint32_t pk2(float a, float b) {
    __nv_bfloat16 x = __float2bfloat16(a), y = __float2bfloat16(b);
    uint16_t xa = *(uint16_t*)&x, yb = *(uint16_t*)&y;
    return (uint32_t)xa | ((uint32_t)yb << 16);
}

__device__ __forceinline__ void poll_cnt(const unsigned* addr, unsigned target) {
    unsigned v;
    for (;;) {
        asm volatile("ld.global.acquire.gpu.u32 %0, [%1];" : "=r"(v) : "l"(addr));
        if (v >= target) break;
        __nanosleep(64);
    }
}

// ---------------------------------------------------------------------------
// Prep kernels (vectorized)
// ---------------------------------------------------------------------------
__global__ void prep_wh(const float* __restrict__ w0, const float* __restrict__ w1,
                        const float* __restrict__ w2, const float* __restrict__ w3)
{
    const int p = blockIdx.x;                 // 0..4095, 128 threads x 8 elems
    const int j = p >> 2, g = p & 3;
    const float* w = (g == 0) ? w0 : (g == 1) ? w1 : (g == 2) ? w2 : w3;
    const float4 v0 = *(const float4*)&w[(size_t)j * HH + threadIdx.x * 8];
    const float4 v1 = *(const float4*)&w[(size_t)j * HH + threadIdx.x * 8 + 4];
    const float f[8] = {v0.x, v0.y, v0.z, v0.w, v1.x, v1.y, v1.z, v1.w};
    float lo[8];
#pragma unroll
    for (int i = 0; i < 8; i++)
        lo[i] = f[i] - __bfloat162float(__float2bfloat16(f[i]));
    size_t base = (size_t)p * HH + threadIdx.x * 8;
    *(uint4*)&g_whi[base] = make_uint4(pk2(f[0], f[1]), pk2(f[2], f[3]), pk2(f[4], f[5]), pk2(f[6], f[7]));
    *(uint4*)&g_wlo[base] = make_uint4(pk2(lo[0], lo[1]), pk2(lo[2], lo[3]), pk2(lo[4], lo[5]), pk2(lo[6], lo[7]));
}

__global__ void prep_wi(const float* __restrict__ w0, const float* __restrict__ w1,
                        const float* __restrict__ w2, const float* __restrict__ w3)
{
    const int p = blockIdx.x;
    const int j = p >> 2, g = p & 3;
    const float* w = (g == 0) ? w0 : (g == 1) ? w1 : (g == 2) ? w2 : w3;
    const float4 v0 = *(const float4*)&w[(size_t)j * II + threadIdx.x * 8];
    const float4 v1 = *(const float4*)&w[(size_t)j * II + threadIdx.x * 8 + 4];
    const float f[8] = {v0.x, v0.y, v0.z, v0.w, v1.x, v1.y, v1.z, v1.w};
    float lo[8];
#pragma unroll
    for (int i = 0; i < 8; i++)
        lo[i] = f[i] - __bfloat162float(__float2bfloat16(f[i]));
    size_t base = (size_t)p * II + threadIdx.x * 8;
    *(uint4*)&g_wihi[base] = make_uint4(pk2(f[0], f[1]), pk2(f[2], f[3]), pk2(f[4], f[5]), pk2(f[6], f[7]));
    *(uint4*)&g_wilo[base] = make_uint4(pk2(lo[0], lo[1]), pk2(lo[2], lo[3]), pk2(lo[4], lo[5]), pk2(lo[6], lo[7]));
}

__global__ void prep_bias(const float* __restrict__ b0, const float* __restrict__ b1,
                          const float* __restrict__ b2, const float* __restrict__ b3)
{
    int p = blockIdx.x * blockDim.x + threadIdx.x;
    int j = p >> 2, g = p & 3;
    const float* b = (g == 0) ? b0 : (g == 1) ? b1 : (g == 2) ? b2 : b3;
    g_bp[p] = b[j];
}

__global__ void prep_x(const float* __restrict__ X)
{
    size_t i = (size_t)blockIdx.x * blockDim.x + threadIdx.x;   // each: 8 floats
    const float4 v0 = ((const float4*)X)[i * 2];
    const float4 v1 = ((const float4*)X)[i * 2 + 1];
    const float f[8] = {v0.x, v0.y, v0.z, v0.w, v1.x, v1.y, v1.z, v1.w};
    float lo[8];
#pragma unroll
    for (int k = 0; k < 8; k++)
        lo[k] = f[k] - __bfloat162float(__float2bfloat16(f[k]));
    ((uint4*)g_xhi)[i] = make_uint4(pk2(f[0], f[1]), pk2(f[2], f[3]), pk2(f[4], f[5]), pk2(f[6], f[7]));
    ((uint4*)g_xlo)[i] = make_uint4(pk2(lo[0], lo[1]), pk2(lo[2], lo[3]), pk2(lo[4], lo[5]), pk2(lo[6], lo[7]));
}

__global__ void prep_h(const float* __restrict__ hx)
{
    int i = blockIdx.x * blockDim.x + threadIdx.x;
    float v = hx[i];
    __nv_bfloat16 hi = __float2bfloat16(v);
    g_hhi[0][i] = hi;
    g_hlo[0][i] = __float2bfloat16(v - __bfloat162float(hi));
    if (i < 8) g_cnt[i] = 0u;                // reset producer counters each replay
}

// ---------------------------------------------------------------------------
// Input projection on tensor cores (3-term split bf16), unchanged
// ---------------------------------------------------------------------------
#define PA_HI 0
#define PA_LO 16384
#define PB_HI 32768
#define PB_LO 49152
#define PSTAGE 65536
#define PSMEM (2 * PSTAGE)   // 131072

__global__ __launch_bounds__(512) void proj_hmma_kernel()
{
    extern __shared__ char smem[];
    const uint32_t sbase = smem_u32(smem);
    const int tid = threadIdx.x;
    const int m0 = blockIdx.y * 128;
    const int n0 = blockIdx.x * 128;

    auto load_chunk = [&](int kc, int st) {
        const uint32_t sb = sbase + st * PSTAGE;
#pragma unroll
        for (int i = 0; i < 2; i++) {
            int u = tid + i * 512;
            int row = u >> 3, c16 = u & 7;
            uint32_t soff = SWZ(row, c16);
            size_t gx = ((size_t)(m0 + row) * II + kc * KCHUNK + c16 * 8) * 2;
            size_t gw = ((size_t)(n0 + row) * II + kc * KCHUNK + c16 * 8) * 2;
            cp_async16(sb + PA_HI + soff, (const char*)g_xhi + gx);
            cp_async16(sb + PA_LO + soff, (const char*)g_xlo + gx);
            cp_async16(sb + PB_HI + soff, (const char*)g_wihi + gw);
            cp_async16(sb + PB_LO + soff, (const char*)g_wilo + gw);
        }
        CP_COMMIT();
    };

    const int wid  = tid >> 5;
    const int lane = tid & 31;
    const int mrow = (wid & 3) * 32;
    const int ncol = (wid >> 2) * 32;
    const int grp  = lane >> 2;
    const int tig  = lane & 3;
    const int tile = lane >> 3;
    const int lr   = lane & 7;

    int a_r[2], b_r[2];
    a_r[0] = mrow + (tile & 1) * 8 + lr;
    a_r[1] = a_r[0] + 16;
    b_r[0] = ncol + (tile >> 1) * 8 + lr;
    b_r[1] = b_r[0] + 16;
    const int a_kt = tile >> 1;
    const int b_kt = tile & 1;

    float acc[2][4][4];
#pragma unroll
    for (int mt = 0; mt < 2; mt++)
#pragma unroll
        for (int n = 0; n < 4; n++)
#pragma unroll
            for (int i = 0; i < 4; i++) acc[mt][n][i] = 0.f;

    load_chunk(0, 0);
    load_chunk(1, 1);

    for (int kc = 0; kc < NCHUNK; kc++) {
        if (kc < NCHUNK - 1) asm volatile("cp.async.wait_group 1;" ::: "memory");
        else                 asm volatile("cp.async.wait_group 0;" ::: "memory");
        __syncthreads();

        const uint32_t sb = sbase + (kc & 1) * PSTAGE;
#pragma unroll
        for (int ks = 0; ks < 4; ks++) {
            uint32_t ah[2][4], al[2][4], bh[2][4], bl[2][4];
#pragma unroll
            for (int mt = 0; mt < 2; mt++) {
                uint32_t ao = a_r[mt] * 128 + ((uint32_t)((ks * 2 + a_kt) ^ (a_r[mt] & 7)) << 4);
                ldsm4(ah[mt], sb + PA_HI + ao);
                ldsm4(al[mt], sb + PA_LO + ao);
            }
#pragma unroll
            for (int nt = 0; nt < 2; nt++) {
                uint32_t bo = b_r[nt] * 128 + ((uint32_t)((ks * 2 + b_kt) ^ (b_r[nt] & 7)) << 4);
                ldsm4(bh[nt], sb + PB_HI + bo);
                ldsm4(bl[nt], sb + PB_LO + bo);
            }
#pragma unroll
            for (int mt = 0; mt < 2; mt++)
#pragma unroll
                for (int nt = 0; nt < 2; nt++) {
                    mma_bf16(acc[mt][2 * nt],     ah[mt], bh[nt][0], bh[nt][1]);
                    mma_bf16(acc[mt][2 * nt + 1], ah[mt], bh[nt][2], bh[nt][3]);
                    mma_bf16(acc[mt][2 * nt],     ah[mt], bl[nt][0], bl[nt][1]);
                    mma_bf16(acc[mt][2 * nt + 1], ah[mt], bl[nt][2], bl[nt][3]);
                    mma_bf16(acc[mt][2 * nt],     al[mt], bh[nt][0], bh[nt][1]);
                    mma_bf16(acc[mt][2 * nt + 1], al[mt], bh[nt][2], bh[nt][3]);
                }
        }
        __syncthreads();
        if (kc + 2 < NCHUNK) load_chunk(kc + 2, kc & 1);
    }

#pragma unroll
    for (int mt = 0; mt < 2; mt++) {
        const int r0 = m0 + mrow + mt * 16 + grp;
#pragma unroll
        for (int n8 = 0; n8 < 4; n8++) {
            const int col = n0 + ncol + n8 * 8 + 2 * tig;
            const float b0 = g_bp[col], b1 = g_bp[col + 1];
            float2 v0 = make_float2(acc[mt][n8][0] + b0, acc[mt][n8][1] + b1);
            float2 v1 = make_float2(acc[mt][n8][2] + b0, acc[mt][n8][3] + b1);
            *(float2*)&g_xp[(size_t)r0 * N4H + col]       = v0;
            *(float2*)&g_xp[(size_t)(r0 + 8) * N4H + col] = v1;
        }
    }
}

// ---------------------------------------------------------------------------
// Persistent recurrent kernel: fine-grained producer-group sync (no global
// barrier), xp prefetched to SMEM, finalize fused.
// ---------------------------------------------------------------------------
#define W_HI_OFF 0
#define W_LO_OFF 65536
#define A_BASE   131072
#define A_ST(s)  (A_BASE + (s) * 16384)
#define XP_OFF   196608            // 8KB xp staging
#define EP_OFF   204800            // 64*36*4 = 9216B epilogue scratch
#define SMEM_TOTAL 214016

__global__ __launch_bounds__(512) void lstm_persist_kernel(
    const float* __restrict__ cx_in, float* __restrict__ out)
{
    extern __shared__ char smem[];
    const uint32_t sbase = smem_u32(smem);
    const int tid = threadIdx.x;
    const int cta = blockIdx.x;
    const int mygrp = cta >> 4;            // producer group 0..7

    // one-time: weights (hi+lo) into SMEM, chunk-major, swizzled
    {
#pragma unroll
        for (int i = 0; i < 8; i++) {
            int u = tid + i * 512;            // 0..4095
            int kc  = u >> 8;
            int row = (u & 255) >> 3;
            int c16 = u & 7;
            uint32_t soff = (uint32_t)(kc * 4096) + SWZ(row, c16);
            size_t   goff = (size_t)(cta * NPC + row) * (HH * 2) + (size_t)kc * 128 + c16 * 16;
            cp_async16(sbase + W_HI_OFF + soff, (const char*)g_whi + goff);
            cp_async16(sbase + W_LO_OFF + soff, (const char*)g_wlo + goff);
        }
        CP_COMMIT();
        asm volatile("cp.async.wait_group 0;" ::: "memory");
        __syncthreads();
    }

    // A-load mapping
    const int arow = tid >> 3;             // 0..63
    const int ac16 = tid & 7;
    const uint32_t a_soff = SWZ(arow, ac16);
    const size_t   a_goff = (size_t)arow * (HH * 2) + ac16 * 16;

    // xp-load mapping (8KB: 64 rows x 128B)
    const uint32_t xp_soff = (uint32_t)(arow * 128 + ac16 * 16);
    const size_t   xp_goff = ((size_t)arow * N4H + cta * NPC + ac16 * 4) * 4;

    // warp/lane mma mapping (warp tile m16n8)
    const int wid  = tid >> 5;
    const int lane = tid & 31;
    const int mrow = (wid & 3) * 16;
    const int ncol = (wid >> 2) * 8;
    const int grp  = lane >> 2;
    const int tig  = lane & 3;
    const int tile = lane >> 3;
    const int lr   = lane & 7;

    const int a_row = mrow + (tile & 1) * 8 + lr;
    const int a_kt  = tile >> 1;
    const int b_row = ncol + lr;
    const int b_kt  = tile & 1;

    const int ep_r = mrow + grp;
    const int ep_c = ncol + 2 * tig;
    float* ep = (float*)(smem + EP_OFF);
    const float* xp_s = (const float*)(smem + XP_OFF);

    // chunk visit order: start at group after own (overlap skew with compute)
    const int cbase = (((mygrp + 1) & 7) << 1);

    for (int t = 0; t < TT; t++) {
        const float* __restrict__ cprev = (t == 0) ? cx_in : g_c;
        const __nv_bfloat16* __restrict__ hhi = g_hhi[t & 1];
        const __nv_bfloat16* __restrict__ hlo = g_hlo[t & 1];
        __nv_bfloat16* __restrict__ nhhi = g_hhi[(t + 1) & 1];
        __nv_bfloat16* __restrict__ nhlo = g_hlo[(t + 1) & 1];
        float* __restrict__ out_t = out + (size_t)t * (BB * HH);
        const float* __restrict__ xp_g = g_xp + (size_t)t * BB * N4H;
        const unsigned tgt = 16u * (unsigned)t;

        auto load_chunk = [&](int seq, bool with_xp) {
            const int cg = (cbase + seq) & 15;
            if (t > 0) poll_cnt(&g_cnt[cg >> 1], tgt);
            const uint32_t sb = sbase + A_ST(seq & 3);
            const size_t kb = (size_t)cg * 128;
            cp_async16(sb + a_soff,        (const char*)hhi + a_goff + kb);
            cp_async16(sb + 8192 + a_soff, (const char*)hlo + a_goff + kb);
            if (with_xp) cp_async16(sbase + XP_OFF + xp_soff, (const char*)xp_g + xp_goff);
            CP_COMMIT();
        };

        load_chunk(0, true);
        load_chunk(1, false);
        load_chunk(2, false);

        float acc_h[4] = {0.f, 0.f, 0.f, 0.f};
        float acc_m[4] = {0.f, 0.f, 0.f, 0.f};

        for (int i = 0; i < NCHUNK; i++) {
            if (i < NCHUNK - 2)       asm volatile("cp.async.wait_group 2;" ::: "memory");
            else if (i == NCHUNK - 2) asm volatile("cp.async.wait_group 1;" ::: "memory");
            else                      asm volatile("cp.async.wait_group 0;" ::: "memory");
            __syncthreads();

            const int cg = (cbase + i) & 15;
            const uint32_t asb = sbase + A_ST(i & 3);
            const uint32_t wb  = (uint32_t)(cg * 4096);
#pragma unroll
            for (int ks = 0; ks < 4; ks++) {
                uint32_t ao = a_row * 128 + ((uint32_t)((ks * 2 + a_kt) ^ (a_row & 7)) << 4);
                uint32_t bo = wb + b_row * 128 + ((uint32_t)((ks * 2 + b_kt) ^ (b_row & 7)) << 4);
                uint32_t ah[4], al[4], bh[2], bl[2];
                ldsm4(ah, asb + ao);
                ldsm2(bh, sbase + W_HI_OFF + bo);
                ldsm4(al, asb + 8192 + ao);
                ldsm2(bl, sbase + W_LO_OFF + bo);
                mma_bf16(acc_h, ah, bh[0], bh[1]);
                mma_bf16(acc_m, ah, bl[0], bl[1]);
                mma_bf16(acc_m, al, bh[0], bh[1]);
            }

            if (i + 3 < NCHUNK) load_chunk(i + 3, false);
        }

        // epilogue
        ep[ep_r * 36 + ep_c]           = acc_h[0] + acc_m[0];
        ep[ep_r * 36 + ep_c + 1]       = acc_h[1] + acc_m[1];
        ep[(ep_r + 8) * 36 + ep_c]     = acc_h[2] + acc_m[2];
        ep[(ep_r + 8) * 36 + ep_c + 1] = acc_h[3] + acc_m[3];
        __syncthreads();

        {
            const int b  = tid >> 3;
            const int jj = tid & 7;
            float4 rv = *(const float4*)&ep[b * 36 + jj * 4];
            float4 xv = *(const float4*)&xp_s[b * 32 + jj * 4];
            float gi = rv.x + xv.x;
            float gf = rv.y + xv.y;
            float ga = rv.z + xv.z;
            float go = rv.w + xv.w;
            float ig = sigmoidf_(gi);
            float fg = sigmoidf_(gf);
            float ag = tanhf(ga);
            float og = sigmoidf_(go);
            int j = cta * 8 + jj;
            float cnew = fg * cprev[b * HH + j] + ig * ag;
            float hnew = og * tanhf(cnew);
            g_c[b * HH + j]   = cnew;
            out_t[b * HH + j] = hnew;
            __nv_bfloat16 hi = __float2bfloat16(hnew);
            nhhi[b * HH + j] = hi;
            nhlo[b * HH + j] = __float2bfloat16(hnew - __bfloat162float(hi));
            if (t == TT - 1) {                     // fused finalize: hy, cy
                const size_t TBH = (size_t)TT * BB * HH;
                out[TBH + b * HH + j]                   = hnew;
                out[TBH + (size_t)BB * HH + b * HH + j] = cnew;
            }
        }
        __syncthreads();

        // signal this CTA's h(t+1) slice is complete
        if (t + 1 < TT && tid == 0) {
            __threadfence();
            atomicAdd(&g_cnt[mygrp], 1u);
        }
    }
}

// ---------------------------------------------------------------------------
extern "C" void kernel_launch(void* const* d_in, const int* in_sizes, int n_in,
                              void* d_out, int out_size)
{
    const float* X    = (const float*)d_in[0];
    const float* hx   = (const float*)d_in[1];
    const float* cx   = (const float*)d_in[2];
    const float* w_ii = (const float*)d_in[3];
    const float* w_fi = (const float*)d_in[4];
    const float* w_ai = (const float*)d_in[5];
    const float* w_oi = (const float*)d_in[6];
    const float* w_ih = (const float*)d_in[7];
    const float* w_fh = (const float*)d_in[8];
    const float* w_ah = (const float*)d_in[9];
    const float* w_oh = (const float*)d_in[10];
    const float* b_i  = (const float*)d_in[11];
    const float* b_f  = (const float*)d_in[12];
    const float* b_a  = (const float*)d_in[13];
    const float* b_o  = (const float*)d_in[14];
    float* out = (float*)d_out;

    (void)in_sizes; (void)n_in; (void)out_size;

    cudaFuncSetAttribute(proj_hmma_kernel,
                         cudaFuncAttributeMaxDynamicSharedMemorySize, PSMEM);
    cudaFuncSetAttribute(lstm_persist_kernel,
                         cudaFuncAttributeMaxDynamicSharedMemorySize, SMEM_TOTAL);

    prep_wh<<<N4H, 128>>>(w_ih, w_fh, w_ah, w_oh);
    prep_wi<<<N4H, 128>>>(w_ii, w_fi, w_ai, w_oi);
    prep_bias<<<N4H / 256, 256>>>(b_i, b_f, b_a, b_o);
    prep_x<<<(int)((size_t)MTOT * II / 8 / 256), 256>>>(X);
    prep_h<<<(BB * HH) / 256, 256>>>(hx);

    dim3 pg(N4H / 128, MTOT / 128);
    proj_hmma_kernel<<<pg, 512, PSMEM>>>();

    lstm_persist_kernel<<<NCTA, 512, SMEM_TOTAL>>>(cx, out);
}

// round 7
// speedup vs baseline: 1.6001x; 1.6001x over previous
#include <cuda_runtime.h>
#include <cuda_bf16.h>
#include <math.h>
#include <stdint.h>

// Problem dims
#define TT   512
#define BB   64
#define II   1024
#define HH   1024
#define N4H  4096
#define MTOT (TT*BB)        // 32768

// Step tiling
#define NCTA    128
#define NPC     32          // gate-output columns (p) per CTA
#define KCHUNK  64
#define NCHUNK  (HH/KCHUNK) // 16

// ---------------------------------------------------------------------------
// Device scratch (allocation-free)
// ---------------------------------------------------------------------------
__device__ float g_xp[(size_t)MTOT * N4H];         // input projections + bias, p-ordered
__device__ float g_c[BB * HH];                     // cell state
__device__ __nv_bfloat16 g_whi[(size_t)N4H * HH];  // Wh hi (p-ordered rows)
__device__ __nv_bfloat16 g_wlo[(size_t)N4H * HH];  // Wh lo
__device__ __nv_bfloat16 g_hhi[2][BB * HH];        // h hi ping-pong
__device__ __nv_bfloat16 g_hlo[2][BB * HH];        // h lo
__device__ __nv_bfloat16 g_xhi[(size_t)MTOT * II]; // X hi
__device__ __nv_bfloat16 g_xlo[(size_t)MTOT * II]; // X lo
__device__ __nv_bfloat16 g_wihi[(size_t)N4H * II]; // Wi hi (p-ordered rows)
__device__ __nv_bfloat16 g_wilo[(size_t)N4H * II]; // Wi lo
__device__ float g_bp[N4H];                        // bias, p-ordered
__device__ unsigned g_bar;                         // grid barrier counter

// ---------------------------------------------------------------------------
// Helpers
// ---------------------------------------------------------------------------
__device__ __forceinline__ uint32_t smem_u32(const void* p) {
    uint32_t a;
    asm("{ .reg .u64 t; cvta.to.shared.u64 t, %1; cvt.u32.u64 %0, t; }" : "=r"(a) : "l"(p));
    return a;
}
__device__ __forceinline__ void cp_async16(uint32_t smem_addr, const void* gptr) {
    asm volatile("cp.async.cg.shared.global [%0], [%1], 16;" :: "r"(smem_addr), "l"(gptr));
}
#define CP_COMMIT() asm volatile("cp.async.commit_group;" ::: "memory")

__device__ __forceinline__ void ldsm4(uint32_t* r, uint32_t addr) {
    asm volatile("ldmatrix.sync.aligned.m8n8.x4.shared.b16 {%0,%1,%2,%3}, [%4];"
                 : "=r"(r[0]), "=r"(r[1]), "=r"(r[2]), "=r"(r[3]) : "r"(addr));
}
__device__ __forceinline__ void mma_bf16(float* d, const uint32_t* a, uint32_t b0, uint32_t b1) {
    asm volatile("mma.sync.aligned.m16n8k16.row.col.f32.bf16.bf16.f32 "
                 "{%0,%1,%2,%3}, {%4,%5,%6,%7}, {%8,%9}, {%0,%1,%2,%3};"
                 : "+f"(d[0]), "+f"(d[1]), "+f"(d[2]), "+f"(d[3])
                 : "r"(a[0]), "r"(a[1]), "r"(a[2]), "r"(a[3]), "r"(b0), "r"(b1));
}
__device__ __forceinline__ float sigmoidf_(float x) { return 1.f / (1.f + expf(-x)); }
#define SWZ(row, c16) ((uint32_t)((row) * 128 + (((c16) ^ ((row) & 7)) << 4)))

__device__ __forceinline__ uint32_t pk2(float a, float b) {
    __nv_bfloat16 x = __float2bfloat16(a), y = __float2bfloat16(b);
    uint16_t xa = *(uint16_t*)&x, yb = *(uint16_t*)&y;
    return (uint32_t)xa | ((uint32_t)yb << 16);
}

// ---------------------------------------------------------------------------
// Prep kernels (vectorized)
// ---------------------------------------------------------------------------
__global__ void prep_wh(const float* __restrict__ w0, const float* __restrict__ w1,
                        const float* __restrict__ w2, const float* __restrict__ w3)
{
    const int p = blockIdx.x;                 // 0..4095, 128 threads x 8 elems
    const int j = p >> 2, g = p & 3;
    const float* w = (g == 0) ? w0 : (g == 1) ? w1 : (g == 2) ? w2 : w3;
    const float4 v0 = *(const float4*)&w[(size_t)j * HH + threadIdx.x * 8];
    const float4 v1 = *(const float4*)&w[(size_t)j * HH + threadIdx.x * 8 + 4];
    const float f[8] = {v0.x, v0.y, v0.z, v0.w, v1.x, v1.y, v1.z, v1.w};
    float lo[8];
#pragma unroll
    for (int i = 0; i < 8; i++)
        lo[i] = f[i] - __bfloat162float(__float2bfloat16(f[i]));
    size_t base = (size_t)p * HH + threadIdx.x * 8;
    *(uint4*)&g_whi[base] = make_uint4(pk2(f[0], f[1]), pk2(f[2], f[3]), pk2(f[4], f[5]), pk2(f[6], f[7]));
    *(uint4*)&g_wlo[base] = make_uint4(pk2(lo[0], lo[1]), pk2(lo[2], lo[3]), pk2(lo[4], lo[5]), pk2(lo[6], lo[7]));
}

__global__ void prep_wi(const float* __restrict__ w0, const float* __restrict__ w1,
                        const float* __restrict__ w2, const float* __restrict__ w3)
{
    const int p = blockIdx.x;
    const int j = p >> 2, g = p & 3;
    const float* w = (g == 0) ? w0 : (g == 1) ? w1 : (g == 2) ? w2 : w3;
    const float4 v0 = *(const float4*)&w[(size_t)j * II + threadIdx.x * 8];
    const float4 v1 = *(const float4*)&w[(size_t)j * II + threadIdx.x * 8 + 4];
    const float f[8] = {v0.x, v0.y, v0.z, v0.w, v1.x, v1.y, v1.z, v1.w};
    float lo[8];
#pragma unroll
    for (int i = 0; i < 8; i++)
        lo[i] = f[i] - __bfloat162float(__float2bfloat16(f[i]));
    size_t base = (size_t)p * II + threadIdx.x * 8;
    *(uint4*)&g_wihi[base] = make_uint4(pk2(f[0], f[1]), pk2(f[2], f[3]), pk2(f[4], f[5]), pk2(f[6], f[7]));
    *(uint4*)&g_wilo[base] = make_uint4(pk2(lo[0], lo[1]), pk2(lo[2], lo[3]), pk2(lo[4], lo[5]), pk2(lo[6], lo[7]));
}

__global__ void prep_bias(const float* __restrict__ b0, const float* __restrict__ b1,
                          const float* __restrict__ b2, const float* __restrict__ b3)
{
    int p = blockIdx.x * blockDim.x + threadIdx.x;
    int j = p >> 2, g = p & 3;
    const float* b = (g == 0) ? b0 : (g == 1) ? b1 : (g == 2) ? b2 : b3;
    g_bp[p] = b[j];
}

__global__ void prep_x(const float* __restrict__ X)
{
    size_t i = (size_t)blockIdx.x * blockDim.x + threadIdx.x;   // each: 8 floats
    const float4 v0 = ((const float4*)X)[i * 2];
    const float4 v1 = ((const float4*)X)[i * 2 + 1];
    const float f[8] = {v0.x, v0.y, v0.z, v0.w, v1.x, v1.y, v1.z, v1.w};
    float lo[8];
#pragma unroll
    for (int k = 0; k < 8; k++)
        lo[k] = f[k] - __bfloat162float(__float2bfloat16(f[k]));
    ((uint4*)g_xhi)[i] = make_uint4(pk2(f[0], f[1]), pk2(f[2], f[3]), pk2(f[4], f[5]), pk2(f[6], f[7]));
    ((uint4*)g_xlo)[i] = make_uint4(pk2(lo[0], lo[1]), pk2(lo[2], lo[3]), pk2(lo[4], lo[5]), pk2(lo[6], lo[7]));
}

__global__ void prep_h(const float* __restrict__ hx)
{
    int i = blockIdx.x * blockDim.x + threadIdx.x;
    float v = hx[i];
    __nv_bfloat16 hi = __float2bfloat16(v);
    g_hhi[0][i] = hi;
    g_hlo[0][i] = __float2bfloat16(v - __bfloat162float(hi));
    if (i == 0) g_bar = 0u;                  // reset barrier each replay
}

// ---------------------------------------------------------------------------
// Input projection on tensor cores (3-term split bf16), unchanged from R5
// ---------------------------------------------------------------------------
#define PA_HI 0
#define PA_LO 16384
#define PB_HI 32768
#define PB_LO 49152
#define PSTAGE 65536
#define PSMEM (2 * PSTAGE)   // 131072

__global__ __launch_bounds__(512) void proj_hmma_kernel()
{
    extern __shared__ char smem[];
    const uint32_t sbase = smem_u32(smem);
    const int tid = threadIdx.x;
    const int m0 = blockIdx.y * 128;
    const int n0 = blockIdx.x * 128;

    auto load_chunk = [&](int kc, int st) {
        const uint32_t sb = sbase + st * PSTAGE;
#pragma unroll
        for (int i = 0; i < 2; i++) {
            int u = tid + i * 512;
            int row = u >> 3, c16 = u & 7;
            uint32_t soff = SWZ(row, c16);
            size_t gx = ((size_t)(m0 + row) * II + kc * KCHUNK + c16 * 8) * 2;
            size_t gw = ((size_t)(n0 + row) * II + kc * KCHUNK + c16 * 8) * 2;
            cp_async16(sb + PA_HI + soff, (const char*)g_xhi + gx);
            cp_async16(sb + PA_LO + soff, (const char*)g_xlo + gx);
            cp_async16(sb + PB_HI + soff, (const char*)g_wihi + gw);
            cp_async16(sb + PB_LO + soff, (const char*)g_wilo + gw);
        }
        CP_COMMIT();
    };

    const int wid  = tid >> 5;
    const int lane = tid & 31;
    const int mrow = (wid & 3) * 32;
    const int ncol = (wid >> 2) * 32;
    const int grp  = lane >> 2;
    const int tig  = lane & 3;
    const int tile = lane >> 3;
    const int lr   = lane & 7;

    int a_r[2], b_r[2];
    a_r[0] = mrow + (tile & 1) * 8 + lr;
    a_r[1] = a_r[0] + 16;
    b_r[0] = ncol + (tile >> 1) * 8 + lr;
    b_r[1] = b_r[0] + 16;
    const int a_kt = tile >> 1;
    const int b_kt = tile & 1;

    float acc[2][4][4];
#pragma unroll
    for (int mt = 0; mt < 2; mt++)
#pragma unroll
        for (int n = 0; n < 4; n++)
#pragma unroll
            for (int i = 0; i < 4; i++) acc[mt][n][i] = 0.f;

    load_chunk(0, 0);
    load_chunk(1, 1);

    for (int kc = 0; kc < NCHUNK; kc++) {
        if (kc < NCHUNK - 1) asm volatile("cp.async.wait_group 1;" ::: "memory");
        else                 asm volatile("cp.async.wait_group 0;" ::: "memory");
        __syncthreads();

        const uint32_t sb = sbase + (kc & 1) * PSTAGE;
#pragma unroll
        for (int ks = 0; ks < 4; ks++) {
            uint32_t ah[2][4], al[2][4], bh[2][4], bl[2][4];
#pragma unroll
            for (int mt = 0; mt < 2; mt++) {
                uint32_t ao = a_r[mt] * 128 + ((uint32_t)((ks * 2 + a_kt) ^ (a_r[mt] & 7)) << 4);
                ldsm4(ah[mt], sb + PA_HI + ao);
                ldsm4(al[mt], sb + PA_LO + ao);
            }
#pragma unroll
            for (int nt = 0; nt < 2; nt++) {
                uint32_t bo = b_r[nt] * 128 + ((uint32_t)((ks * 2 + b_kt) ^ (b_r[nt] & 7)) << 4);
                ldsm4(bh[nt], sb + PB_HI + bo);
                ldsm4(bl[nt], sb + PB_LO + bo);
            }
#pragma unroll
            for (int mt = 0; mt < 2; mt++)
#pragma unroll
                for (int nt = 0; nt < 2; nt++) {
                    mma_bf16(acc[mt][2 * nt],     ah[mt], bh[nt][0], bh[nt][1]);
                    mma_bf16(acc[mt][2 * nt + 1], ah[mt], bh[nt][2], bh[nt][3]);
                    mma_bf16(acc[mt][2 * nt],     ah[mt], bl[nt][0], bl[nt][1]);
                    mma_bf16(acc[mt][2 * nt + 1], ah[mt], bl[nt][2], bl[nt][3]);
                    mma_bf16(acc[mt][2 * nt],     al[mt], bh[nt][0], bh[nt][1]);
                    mma_bf16(acc[mt][2 * nt + 1], al[mt], bh[nt][2], bh[nt][3]);
                }
        }
        __syncthreads();
        if (kc + 2 < NCHUNK) load_chunk(kc + 2, kc & 1);
    }

#pragma unroll
    for (int mt = 0; mt < 2; mt++) {
        const int r0 = m0 + mrow + mt * 16 + grp;
#pragma unroll
        for (int n8 = 0; n8 < 4; n8++) {
            const int col = n0 + ncol + n8 * 8 + 2 * tig;
            const float b0 = g_bp[col], b1 = g_bp[col + 1];
            float2 v0 = make_float2(acc[mt][n8][0] + b0, acc[mt][n8][1] + b1);
            float2 v1 = make_float2(acc[mt][n8][2] + b0, acc[mt][n8][3] + b1);
            *(float2*)&g_xp[(size_t)r0 * N4H + col]       = v0;
            *(float2*)&g_xp[(size_t)(r0 + 8) * N4H + col] = v1;
        }
    }
}

// ---------------------------------------------------------------------------
// Persistent recurrent kernel.
// 16 warps = 2 m-pos x 2 n-pos x 4 k-slices. Warp tile m32n16, each warp
// handles one kstep (16 K-elems) of every chunk -> half the LDSM traffic.
// K-partials reduced via smem in the epilogue. Single global barrier per
// step (tid0 polls). Weights SMEM-resident; A 3-stage cp.async pipeline.
// ---------------------------------------------------------------------------
#define W_HI_OFF 0
#define W_LO_OFF 65536
#define A_BASE   131072
#define A_ST(s)  (A_BASE + (s) * 16384)     // 3 stages x 16KB (hi 8K + lo 8K)
#define EP_OFF   A_BASE                     // epilogue scratch overlays A stages
#define XP_OFF   180224                     // A_BASE + 49152
#define SMEM_TOTAL 188416                   // 184KB

__global__ __launch_bounds__(512) void lstm_persist_kernel(
    const float* __restrict__ cx_in, float* __restrict__ out)
{
    extern __shared__ char smem[];
    const uint32_t sbase = smem_u32(smem);
    const int tid = threadIdx.x;
    const int cta = blockIdx.x;

    // one-time: weights (hi+lo) into SMEM, chunk-major, swizzled
    {
#pragma unroll
        for (int i = 0; i < 8; i++) {
            int u = tid + i * 512;            // 0..4095
            int kc  = u >> 8;
            int row = (u & 255) >> 3;
            int c16 = u & 7;
            uint32_t soff = (uint32_t)(kc * 4096) + SWZ(row, c16);
            size_t   goff = (size_t)(cta * NPC + row) * (HH * 2) + (size_t)kc * 128 + c16 * 16;
            cp_async16(sbase + W_HI_OFF + soff, (const char*)g_whi + goff);
            cp_async16(sbase + W_LO_OFF + soff, (const char*)g_wlo + goff);
        }
        CP_COMMIT();
        asm volatile("cp.async.wait_group 0;" ::: "memory");
        __syncthreads();
    }

    // A-load mapping: 1 hi + 1 lo cp.async per thread per chunk
    const int arow = tid >> 3;             // 0..63
    const int ac16 = tid & 7;
    const uint32_t a_soff = SWZ(arow, ac16);
    const size_t   a_goff = (size_t)arow * (HH * 2) + ac16 * 16;

    // xp staging (8KB: 64 rows x 32 floats)
    const uint32_t xp_soff = (uint32_t)(arow * 128 + ac16 * 16);
    const size_t   xp_goff = ((size_t)arow * N4H + cta * NPC + ac16 * 4) * 4;

    // warp/lane mapping: m32n16 tile, in-chunk k-split
    const int wid  = tid >> 5;
    const int lane = tid & 31;
    const int ks   = wid & 3;              // k-slice (kstep within chunk)
    const int mpos = (wid >> 2) & 1;       // rows mpos*32
    const int npos = wid >> 3;             // cols npos*16
    const int grp  = lane >> 2;
    const int tig  = lane & 3;
    const int tile = lane >> 3;
    const int lr   = lane & 7;

    const int a_row0 = mpos * 32 + (tile & 1) * 8 + lr;
    const int a_kt   = tile >> 1;
    const int b_row  = npos * 16 + (tile >> 1) * 8 + lr;
    const int b_kt   = tile & 1;

    const uint32_t a_off0 = (uint32_t)(a_row0 * 128) +
                            ((uint32_t)((ks * 2 + a_kt) ^ (a_row0 & 7)) << 4);
    const uint32_t a_off1 = a_off0 + 16 * 128;
    const uint32_t b_off  = (uint32_t)(b_row * 128) +
                            ((uint32_t)((ks * 2 + b_kt) ^ (b_row & 7)) << 4);

    float* ep = (float*)(smem + EP_OFF);   // [4 ks][64 rows][36 stride]
    const float* xp_s = (const float*)(smem + XP_OFF);
    float* myep = ep + ks * 2304;

    for (int t = 0; t < TT; t++) {
        const float* __restrict__ cprev = (t == 0) ? cx_in : g_c;
        const __nv_bfloat16* __restrict__ hhi = g_hhi[t & 1];
        const __nv_bfloat16* __restrict__ hlo = g_hlo[t & 1];
        __nv_bfloat16* __restrict__ nhhi = g_hhi[(t + 1) & 1];
        __nv_bfloat16* __restrict__ nhlo = g_hlo[(t + 1) & 1];
        float* __restrict__ out_t = out + (size_t)t * (BB * HH);
        const float* __restrict__ xp_g = g_xp + (size_t)t * BB * N4H;

        auto load_chunk = [&](int kc, int st, bool with_xp) {
            const uint32_t sb = sbase + A_ST(st);
            const size_t kb = (size_t)kc * 128;
            cp_async16(sb + a_soff,        (const char*)hhi + a_goff + kb);
            cp_async16(sb + 8192 + a_soff, (const char*)hlo + a_goff + kb);
            if (with_xp) cp_async16(sbase + XP_OFF + xp_soff, (const char*)xp_g + xp_goff);
            CP_COMMIT();
        };

        load_chunk(0, 0, true);
        load_chunk(1, 1, false);

        float acc_h[2][2][4];
        float acc_m[2][2][4];
#pragma unroll
        for (int mt = 0; mt < 2; mt++)
#pragma unroll
            for (int nt = 0; nt < 2; nt++)
#pragma unroll
                for (int i = 0; i < 4; i++) { acc_h[mt][nt][i] = 0.f; acc_m[mt][nt][i] = 0.f; }

        int stC = 0;                        // compute stage (c % 3)
        int stL = 2;                        // load stage ((c+2) % 3)
        for (int c = 0; c < NCHUNK; c++) {
            if (c < NCHUNK - 1) asm volatile("cp.async.wait_group 1;" ::: "memory");
            else                asm volatile("cp.async.wait_group 0;" ::: "memory");
            __syncthreads();

            const uint32_t asb = sbase + A_ST(stC);
            const uint32_t whb = sbase + W_HI_OFF + (uint32_t)(c * 4096);

            uint32_t ah0[4], ah1[4], al0[4], al1[4], bh[4], bl[4];
            ldsm4(ah0, asb + a_off0);
            ldsm4(ah1, asb + a_off1);
            ldsm4(bh,  whb + b_off);
            ldsm4(al0, asb + 8192 + a_off0);
            ldsm4(al1, asb + 8192 + a_off1);
            ldsm4(bl,  whb + 65536 + b_off);

            mma_bf16(acc_h[0][0], ah0, bh[0], bh[1]);
            mma_bf16(acc_h[0][1], ah0, bh[2], bh[3]);
            mma_bf16(acc_h[1][0], ah1, bh[0], bh[1]);
            mma_bf16(acc_h[1][1], ah1, bh[2], bh[3]);
            mma_bf16(acc_m[0][0], ah0, bl[0], bl[1]);
            mma_bf16(acc_m[0][1], ah0, bl[2], bl[3]);
            mma_bf16(acc_m[1][0], ah1, bl[0], bl[1]);
            mma_bf16(acc_m[1][1], ah1, bl[2], bl[3]);
            mma_bf16(acc_m[0][0], al0, bh[0], bh[1]);
            mma_bf16(acc_m[0][1], al0, bh[2], bh[3]);
            mma_bf16(acc_m[1][0], al1, bh[0], bh[1]);
            mma_bf16(acc_m[1][1], al1, bh[2], bh[3]);

            if (c + 2 < NCHUNK) load_chunk(c + 2, stL, false);
            stC = (stC == 2) ? 0 : stC + 1;
            stL = (stL == 2) ? 0 : stL + 1;
        }

        // ---- k-partial reduction + fused LSTM epilogue ----
        __syncthreads();                   // MMA reads done before ep overlays A
#pragma unroll
        for (int mt = 0; mt < 2; mt++)
#pragma unroll
            for (int nt = 0; nt < 2; nt++) {
                const int r  = mpos * 32 + mt * 16 + grp;
                const int ci = npos * 16 + nt * 8 + 2 * tig;
                myep[r * 36 + ci]           = acc_h[mt][nt][0] + acc_m[mt][nt][0];
                myep[r * 36 + ci + 1]       = acc_h[mt][nt][1] + acc_m[mt][nt][1];
                myep[(r + 8) * 36 + ci]     = acc_h[mt][nt][2] + acc_m[mt][nt][2];
                myep[(r + 8) * 36 + ci + 1] = acc_h[mt][nt][3] + acc_m[mt][nt][3];
            }
        __syncthreads();

        {
            const int b  = tid >> 3;
            const int jj = tid & 7;
            float4 r0 = *(const float4*)&ep[b * 36 + jj * 4];
            float4 r1 = *(const float4*)&ep[2304 + b * 36 + jj * 4];
            float4 r2 = *(const float4*)&ep[4608 + b * 36 + jj * 4];
            float4 r3 = *(const float4*)&ep[6912 + b * 36 + jj * 4];
            float4 xv = *(const float4*)&xp_s[b * 32 + jj * 4];
            float gi = (r0.x + r1.x) + (r2.x + r3.x) + xv.x;
            float gf = (r0.y + r1.y) + (r2.y + r3.y) + xv.y;
            float ga = (r0.z + r1.z) + (r2.z + r3.z) + xv.z;
            float go = (r0.w + r1.w) + (r2.w + r3.w) + xv.w;
            float ig = sigmoidf_(gi);
            float fg = sigmoidf_(gf);
            float ag = tanhf(ga);
            float og = sigmoidf_(go);
            int j = cta * 8 + jj;
            float cnew = fg * cprev[b * HH + j] + ig * ag;
            float hnew = og * tanhf(cnew);
            g_c[b * HH + j]   = cnew;
            out_t[b * HH + j] = hnew;
            __nv_bfloat16 hi = __float2bfloat16(hnew);
            nhhi[b * HH + j] = hi;
            nhlo[b * HH + j] = __float2bfloat16(hnew - __bfloat162float(hi));
            if (t == TT - 1) {             // fused finalize: hy, cy
                const size_t TBH = (size_t)TT * BB * HH;
                out[TBH + b * HH + j]                   = hnew;
                out[TBH + (size_t)BB * HH + b * HH + j] = cnew;
            }
        }

        // ---- global barrier (tid0-only poll) ----
        if (t + 1 < TT) {
            __syncthreads();
            if (tid == 0) {
                __threadfence();
                atomicAdd(&g_bar, 1u);
                const unsigned target = (unsigned)NCTA * (unsigned)(t + 1);
                unsigned v;
                do {
                    asm volatile("ld.global.acquire.gpu.u32 %0, [%1];"
                                 : "=r"(v) : "l"(&g_bar));
                    if (v < target) __nanosleep(32);
                } while (v < target);
            }
            __syncthreads();
        }
    }
}

// ---------------------------------------------------------------------------
extern "C" void kernel_launch(void* const* d_in, const int* in_sizes, int n_in,
                              void* d_out, int out_size)
{
    const float* X    = (const float*)d_in[0];
    const float* hx   = (const float*)d_in[1];
    const float* cx   = (const float*)d_in[2];
    const float* w_ii = (const float*)d_in[3];
    const float* w_fi = (const float*)d_in[4];
    const float* w_ai = (const float*)d_in[5];
    const float* w_oi = (const float*)d_in[6];
    const float* w_ih = (const float*)d_in[7];
    const float* w_fh = (const float*)d_in[8];
    const float* w_ah = (const float*)d_in[9];
    const float* w_oh = (const float*)d_in[10];
    const float* b_i  = (const float*)d_in[11];
    const float* b_f  = (const float*)d_in[12];
    const float* b_a  = (const float*)d_in[13];
    const float* b_o  = (const float*)d_in[14];
    float* out = (float*)d_out;

    (void)in_sizes; (void)n_in; (void)out_size;

    cudaFuncSetAttribute(proj_hmma_kernel,
                         cudaFuncAttributeMaxDynamicSharedMemorySize, PSMEM);
    cudaFuncSetAttribute(lstm_persist_kernel,
                         cudaFuncAttributeMaxDynamicSharedMemorySize, SMEM_TOTAL);

    prep_wh<<<N4H, 128>>>(w_ih, w_fh, w_ah, w_oh);
    prep_wi<<<N4H, 128>>>(w_ii, w_fi, w_ai, w_oi);
    prep_bias<<<N4H / 256, 256>>>(b_i, b_f, b_a, b_o);
    prep_x<<<(int)((size_t)MTOT * II / 8 / 256), 256>>>(X);
    prep_h<<<(BB * HH) / 256, 256>>>(hx);

    dim3 pg(N4H / 128, MTOT / 128);
    proj_hmma_kernel<<<pg, 512, PSMEM>>>();

    lstm_persist_kernel<<<NCTA, 512, SMEM_TOTAL>>>(cx, out);
}

// round 8
// speedup vs baseline: 1.6967x; 1.0604x over previous
#include <cuda_runtime.h>
#include <cuda_bf16.h>
#include <math.h>
#include <stdint.h>

// Problem dims
#define TT   512
#define BB   64
#define II   1024
#define HH   1024
#define N4H  4096
#define MTOT (TT*BB)        // 32768

// Step tiling
#define NCTA    128
#define NPC     32          // gate-output columns (p) per CTA
#define KCHUNK  64
#define NCHUNK  (HH/KCHUNK) // 16

// ---------------------------------------------------------------------------
// Device scratch (allocation-free)
// ---------------------------------------------------------------------------
__device__ float g_xp[(size_t)MTOT * N4H];         // input projections + bias, p-ordered
__device__ float g_c[BB * HH];                     // cell state
__device__ __nv_bfloat16 g_whi[(size_t)N4H * HH];  // Wh hi (p-ordered rows)
__device__ __nv_bfloat16 g_wlo[(size_t)N4H * HH];  // Wh lo
__device__ __nv_bfloat16 g_hhi[2][BB * HH];        // h hi ping-pong
__device__ __nv_bfloat16 g_hlo[2][BB * HH];        // h lo
__device__ __nv_bfloat16 g_xhi[(size_t)MTOT * II]; // X hi
__device__ __nv_bfloat16 g_xlo[(size_t)MTOT * II]; // X lo
__device__ __nv_bfloat16 g_wihi[(size_t)N4H * II]; // Wi hi (p-ordered rows)
__device__ __nv_bfloat16 g_wilo[(size_t)N4H * II]; // Wi lo
__device__ float g_bp[N4H];                        // bias, p-ordered
__device__ unsigned g_bar;                         // grid barrier counter

// ---------------------------------------------------------------------------
// Helpers
// ---------------------------------------------------------------------------
__device__ __forceinline__ uint32_t smem_u32(const void* p) {
    uint32_t a;
    asm("{ .reg .u64 t; cvta.to.shared.u64 t, %1; cvt.u32.u64 %0, t; }" : "=r"(a) : "l"(p));
    return a;
}
__device__ __forceinline__ void cp_async16(uint32_t smem_addr, const void* gptr) {
    asm volatile("cp.async.cg.shared.global [%0], [%1], 16;" :: "r"(smem_addr), "l"(gptr));
}
#define CP_COMMIT() asm volatile("cp.async.commit_group;" ::: "memory")

__device__ __forceinline__ void ldsm4(uint32_t* r, uint32_t addr) {
    asm volatile("ldmatrix.sync.aligned.m8n8.x4.shared.b16 {%0,%1,%2,%3}, [%4];"
                 : "=r"(r[0]), "=r"(r[1]), "=r"(r[2]), "=r"(r[3]) : "r"(addr));
}
__device__ __forceinline__ void mma_bf16(float* d, const uint32_t* a, uint32_t b0, uint32_t b1) {
    asm volatile("mma.sync.aligned.m16n8k16.row.col.f32.bf16.bf16.f32 "
                 "{%0,%1,%2,%3}, {%4,%5,%6,%7}, {%8,%9}, {%0,%1,%2,%3};"
                 : "+f"(d[0]), "+f"(d[1]), "+f"(d[2]), "+f"(d[3])
                 : "r"(a[0]), "r"(a[1]), "r"(a[2]), "r"(a[3]), "r"(b0), "r"(b1));
}
__device__ __forceinline__ float sigmoidf_(float x) { return 1.f / (1.f + expf(-x)); }
#define SWZ(row, c16) ((uint32_t)((row) * 128 + (((c16) ^ ((row) & 7)) << 4)))

__device__ __forceinline__ uint32_t pk2(float a, float b) {
    __nv_bfloat16 x = __float2bfloat16(a), y = __float2bfloat16(b);
    uint16_t xa = *(uint16_t*)&x, yb = *(uint16_t*)&y;
    return (uint32_t)xa | ((uint32_t)yb << 16);
}

// ---------------------------------------------------------------------------
// Prep kernels (vectorized)
// ---------------------------------------------------------------------------
__global__ void prep_wh(const float* __restrict__ w0, const float* __restrict__ w1,
                        const float* __restrict__ w2, const float* __restrict__ w3)
{
    const int p = blockIdx.x;                 // 0..4095, 128 threads x 8 elems
    const int j = p >> 2, g = p & 3;
    const float* w = (g == 0) ? w0 : (g == 1) ? w1 : (g == 2) ? w2 : w3;
    const float4 v0 = *(const float4*)&w[(size_t)j * HH + threadIdx.x * 8];
    const float4 v1 = *(const float4*)&w[(size_t)j * HH + threadIdx.x * 8 + 4];
    const float f[8] = {v0.x, v0.y, v0.z, v0.w, v1.x, v1.y, v1.z, v1.w};
    float lo[8];
#pragma unroll
    for (int i = 0; i < 8; i++)
        lo[i] = f[i] - __bfloat162float(__float2bfloat16(f[i]));
    size_t base = (size_t)p * HH + threadIdx.x * 8;
    *(uint4*)&g_whi[base] = make_uint4(pk2(f[0], f[1]), pk2(f[2], f[3]), pk2(f[4], f[5]), pk2(f[6], f[7]));
    *(uint4*)&g_wlo[base] = make_uint4(pk2(lo[0], lo[1]), pk2(lo[2], lo[3]), pk2(lo[4], lo[5]), pk2(lo[6], lo[7]));
}

__global__ void prep_wi(const float* __restrict__ w0, const float* __restrict__ w1,
                        const float* __restrict__ w2, const float* __restrict__ w3)
{
    const int p = blockIdx.x;
    const int j = p >> 2, g = p & 3;
    const float* w = (g == 0) ? w0 : (g == 1) ? w1 : (g == 2) ? w2 : w3;
    const float4 v0 = *(const float4*)&w[(size_t)j * II + threadIdx.x * 8];
    const float4 v1 = *(const float4*)&w[(size_t)j * II + threadIdx.x * 8 + 4];
    const float f[8] = {v0.x, v0.y, v0.z, v0.w, v1.x, v1.y, v1.z, v1.w};
    float lo[8];
#pragma unroll
    for (int i = 0; i < 8; i++)
        lo[i] = f[i] - __bfloat162float(__float2bfloat16(f[i]));
    size_t base = (size_t)p * II + threadIdx.x * 8;
    *(uint4*)&g_wihi[base] = make_uint4(pk2(f[0], f[1]), pk2(f[2], f[3]), pk2(f[4], f[5]), pk2(f[6], f[7]));
    *(uint4*)&g_wilo[base] = make_uint4(pk2(lo[0], lo[1]), pk2(lo[2], lo[3]), pk2(lo[4], lo[5]), pk2(lo[6], lo[7]));
}

__global__ void prep_bias(const float* __restrict__ b0, const float* __restrict__ b1,
                          const float* __restrict__ b2, const float* __restrict__ b3)
{
    int p = blockIdx.x * blockDim.x + threadIdx.x;
    int j = p >> 2, g = p & 3;
    const float* b = (g == 0) ? b0 : (g == 1) ? b1 : (g == 2) ? b2 : b3;
    g_bp[p] = b[j];
}

__global__ void prep_x(const float* __restrict__ X)
{
    size_t i = (size_t)blockIdx.x * blockDim.x + threadIdx.x;   // each: 8 floats
    const float4 v0 = ((const float4*)X)[i * 2];
    const float4 v1 = ((const float4*)X)[i * 2 + 1];
    const float f[8] = {v0.x, v0.y, v0.z, v0.w, v1.x, v1.y, v1.z, v1.w};
    float lo[8];
#pragma unroll
    for (int k = 0; k < 8; k++)
        lo[k] = f[k] - __bfloat162float(__float2bfloat16(f[k]));
    ((uint4*)g_xhi)[i] = make_uint4(pk2(f[0], f[1]), pk2(f[2], f[3]), pk2(f[4], f[5]), pk2(f[6], f[7]));
    ((uint4*)g_xlo)[i] = make_uint4(pk2(lo[0], lo[1]), pk2(lo[2], lo[3]), pk2(lo[4], lo[5]), pk2(lo[6], lo[7]));
}

__global__ void prep_h(const float* __restrict__ hx)
{
    int i = blockIdx.x * blockDim.x + threadIdx.x;
    float v = hx[i];
    __nv_bfloat16 hi = __float2bfloat16(v);
    g_hhi[0][i] = hi;
    g_hlo[0][i] = __float2bfloat16(v - __bfloat162float(hi));
    if (i == 0) g_bar = 0u;                  // reset barrier each replay
}

// ---------------------------------------------------------------------------
// Input projection on tensor cores (3-term split bf16)
// ---------------------------------------------------------------------------
#define PA_HI 0
#define PA_LO 16384
#define PB_HI 32768
#define PB_LO 49152
#define PSTAGE 65536
#define PSMEM (2 * PSTAGE)   // 131072

__global__ __launch_bounds__(512) void proj_hmma_kernel()
{
    extern __shared__ char smem[];
    const uint32_t sbase = smem_u32(smem);
    const int tid = threadIdx.x;
    const int m0 = blockIdx.y * 128;
    const int n0 = blockIdx.x * 128;

    auto load_chunk = [&](int kc, int st) {
        const uint32_t sb = sbase + st * PSTAGE;
#pragma unroll
        for (int i = 0; i < 2; i++) {
            int u = tid + i * 512;
            int row = u >> 3, c16 = u & 7;
            uint32_t soff = SWZ(row, c16);
            size_t gx = ((size_t)(m0 + row) * II + kc * KCHUNK + c16 * 8) * 2;
            size_t gw = ((size_t)(n0 + row) * II + kc * KCHUNK + c16 * 8) * 2;
            cp_async16(sb + PA_HI + soff, (const char*)g_xhi + gx);
            cp_async16(sb + PA_LO + soff, (const char*)g_xlo + gx);
            cp_async16(sb + PB_HI + soff, (const char*)g_wihi + gw);
            cp_async16(sb + PB_LO + soff, (const char*)g_wilo + gw);
        }
        CP_COMMIT();
    };

    const int wid  = tid >> 5;
    const int lane = tid & 31;
    const int mrow = (wid & 3) * 32;
    const int ncol = (wid >> 2) * 32;
    const int grp  = lane >> 2;
    const int tig  = lane & 3;
    const int tile = lane >> 3;
    const int lr   = lane & 7;

    int a_r[2], b_r[2];
    a_r[0] = mrow + (tile & 1) * 8 + lr;
    a_r[1] = a_r[0] + 16;
    b_r[0] = ncol + (tile >> 1) * 8 + lr;
    b_r[1] = b_r[0] + 16;
    const int a_kt = tile >> 1;
    const int b_kt = tile & 1;

    float acc[2][4][4];
#pragma unroll
    for (int mt = 0; mt < 2; mt++)
#pragma unroll
        for (int n = 0; n < 4; n++)
#pragma unroll
            for (int i = 0; i < 4; i++) acc[mt][n][i] = 0.f;

    load_chunk(0, 0);
    load_chunk(1, 1);

    for (int kc = 0; kc < NCHUNK; kc++) {
        if (kc < NCHUNK - 1) asm volatile("cp.async.wait_group 1;" ::: "memory");
        else                 asm volatile("cp.async.wait_group 0;" ::: "memory");
        __syncthreads();

        const uint32_t sb = sbase + (kc & 1) * PSTAGE;
#pragma unroll
        for (int ks = 0; ks < 4; ks++) {
            uint32_t ah[2][4], al[2][4], bh[2][4], bl[2][4];
#pragma unroll
            for (int mt = 0; mt < 2; mt++) {
                uint32_t ao = a_r[mt] * 128 + ((uint32_t)((ks * 2 + a_kt) ^ (a_r[mt] & 7)) << 4);
                ldsm4(ah[mt], sb + PA_HI + ao);
                ldsm4(al[mt], sb + PA_LO + ao);
            }
#pragma unroll
            for (int nt = 0; nt < 2; nt++) {
                uint32_t bo = b_r[nt] * 128 + ((uint32_t)((ks * 2 + b_kt) ^ (b_r[nt] & 7)) << 4);
                ldsm4(bh[nt], sb + PB_HI + bo);
                ldsm4(bl[nt], sb + PB_LO + bo);
            }
#pragma unroll
            for (int mt = 0; mt < 2; mt++)
#pragma unroll
                for (int nt = 0; nt < 2; nt++) {
                    mma_bf16(acc[mt][2 * nt],     ah[mt], bh[nt][0], bh[nt][1]);
                    mma_bf16(acc[mt][2 * nt + 1], ah[mt], bh[nt][2], bh[nt][3]);
                    mma_bf16(acc[mt][2 * nt],     ah[mt], bl[nt][0], bl[nt][1]);
                    mma_bf16(acc[mt][2 * nt + 1], ah[mt], bl[nt][2], bl[nt][3]);
                    mma_bf16(acc[mt][2 * nt],     al[mt], bh[nt][0], bh[nt][1]);
                    mma_bf16(acc[mt][2 * nt + 1], al[mt], bh[nt][2], bh[nt][3]);
                }
        }
        __syncthreads();
        if (kc + 2 < NCHUNK) load_chunk(kc + 2, kc & 1);
    }

#pragma unroll
    for (int mt = 0; mt < 2; mt++) {
        const int r0 = m0 + mrow + mt * 16 + grp;
#pragma unroll
        for (int n8 = 0; n8 < 4; n8++) {
            const int col = n0 + ncol + n8 * 8 + 2 * tig;
            const float b0 = g_bp[col], b1 = g_bp[col + 1];
            float2 v0 = make_float2(acc[mt][n8][0] + b0, acc[mt][n8][1] + b1);
            float2 v1 = make_float2(acc[mt][n8][2] + b0, acc[mt][n8][3] + b1);
            *(float2*)&g_xp[(size_t)r0 * N4H + col]       = v0;
            *(float2*)&g_xp[(size_t)(r0 + 8) * N4H + col] = v1;
        }
    }
}

// ---------------------------------------------------------------------------
// Persistent recurrent kernel.
// 256 threads / 8 warps = (2 m-pos x 4 k-slices). Warp tile m32 x n32 (full
// CTA width) -> every A/B fragment read exactly ONCE: 32KB LDSM per chunk.
// Loads for chunk c+2 issued BEFORE the MMA block (3-stage ring makes the
// target stage free). K-partials reduced via smem. Weights SMEM-resident.
// Single tid0-poll global barrier per step. Finalize fused.
// ---------------------------------------------------------------------------
#define W_HI_OFF 0
#define W_LO_OFF 65536
#define A_BASE   131072
#define A_ST(s)  (A_BASE + (s) * 16384)     // 3 stages x 16KB (hi 8K + lo 8K)
#define EP_OFF   A_BASE                     // epilogue scratch overlays A (36KB<=48KB)
#define XP_OFF   180224                     // A_BASE + 49152
#define SMEM_TOTAL 188416                   // 184KB

__global__ __launch_bounds__(256) void lstm_persist_kernel(
    const float* __restrict__ cx_in, float* __restrict__ out)
{
    extern __shared__ char smem[];
    const uint32_t sbase = smem_u32(smem);
    const int tid = threadIdx.x;
    const int cta = blockIdx.x;

    // one-time: weights (hi+lo) into SMEM, chunk-major, swizzled
    {
#pragma unroll
        for (int i = 0; i < 16; i++) {
            int u = tid + i * 256;            // 0..4095
            int kc  = u >> 8;
            int row = (u & 255) >> 3;
            int c16 = u & 7;
            uint32_t soff = (uint32_t)(kc * 4096) + SWZ(row, c16);
            size_t   goff = (size_t)(cta * NPC + row) * (HH * 2) + (size_t)kc * 128 + c16 * 16;
            cp_async16(sbase + W_HI_OFF + soff, (const char*)g_whi + goff);
            cp_async16(sbase + W_LO_OFF + soff, (const char*)g_wlo + goff);
        }
        CP_COMMIT();
        asm volatile("cp.async.wait_group 0;" ::: "memory");
        __syncthreads();
    }

    // A-load mapping: 2 hi + 2 lo cp.async per thread per chunk
    uint32_t a_soff[2];
    size_t   a_goff[2];
    uint32_t xp_soff[2];
    size_t   xp_goff[2];
#pragma unroll
    for (int i = 0; i < 2; i++) {
        int u = tid + i * 256;               // 0..511
        int row = u >> 3, c16 = u & 7;
        a_soff[i] = SWZ(row, c16);
        a_goff[i] = (size_t)row * (HH * 2) + c16 * 16;
        xp_soff[i] = (uint32_t)(u * 16);
        xp_goff[i] = ((size_t)row * N4H + cta * NPC + c16 * 4) * 4;
    }

    // warp/lane mapping: (mpos, ks), warp tile m32 x n32
    const int wid  = tid >> 5;
    const int lane = tid & 31;
    const int ks   = wid & 3;              // k-slice (kstep within chunk)
    const int mpos = wid >> 2;             // rows mpos*32
    const int grp  = lane >> 2;
    const int tig  = lane & 3;
    const int tile = lane >> 3;
    const int lr   = lane & 7;

    const int a_row0 = mpos * 32 + (tile & 1) * 8 + lr;
    const int a_kt   = tile >> 1;
    const int b_row  = (tile >> 1) * 8 + lr;   // rows 0..15 of B (n 0..15)
    const int b_kt   = tile & 1;

    const uint32_t a_off0 = (uint32_t)(a_row0 * 128) +
                            ((uint32_t)((ks * 2 + a_kt) ^ (a_row0 & 7)) << 4);
    const uint32_t a_off1 = a_off0 + 16 * 128;
    const uint32_t b_off0 = (uint32_t)(b_row * 128) +
                            ((uint32_t)((ks * 2 + b_kt) ^ (b_row & 7)) << 4);
    const uint32_t b_off1 = b_off0 + 16 * 128;

    float* ep = (float*)(smem + EP_OFF);   // [4 ks][64 rows][36 stride]
    const float* xp_s = (const float*)(smem + XP_OFF);
    float* myep = ep + ks * 2304;

    for (int t = 0; t < TT; t++) {
        const float* __restrict__ cprev = (t == 0) ? cx_in : g_c;
        const __nv_bfloat16* __restrict__ hhi = g_hhi[t & 1];
        const __nv_bfloat16* __restrict__ hlo = g_hlo[t & 1];
        __nv_bfloat16* __restrict__ nhhi = g_hhi[(t + 1) & 1];
        __nv_bfloat16* __restrict__ nhlo = g_hlo[(t + 1) & 1];
        float* __restrict__ out_t = out + (size_t)t * (BB * HH);
        const float* __restrict__ xp_g = g_xp + (size_t)t * BB * N4H;

        auto load_chunk = [&](int kc, int st, bool with_xp) {
            const uint32_t sb = sbase + A_ST(st);
            const size_t kb = (size_t)kc * 128;
#pragma unroll
            for (int i = 0; i < 2; i++) {
                cp_async16(sb + a_soff[i],        (const char*)hhi + a_goff[i] + kb);
                cp_async16(sb + 8192 + a_soff[i], (const char*)hlo + a_goff[i] + kb);
                if (with_xp) cp_async16(sbase + XP_OFF + xp_soff[i], (const char*)xp_g + xp_goff[i]);
            }
            CP_COMMIT();
        };

        load_chunk(0, 0, true);
        load_chunk(1, 1, false);

        float acc_h[2][4][4];
        float acc_m[2][4][4];
#pragma unroll
        for (int mt = 0; mt < 2; mt++)
#pragma unroll
            for (int nt = 0; nt < 4; nt++)
#pragma unroll
                for (int i = 0; i < 4; i++) { acc_h[mt][nt][i] = 0.f; acc_m[mt][nt][i] = 0.f; }

        int stC = 0;                        // compute stage (c % 3)
        int stL = 2;                        // load stage ((c+2) % 3)
        for (int c = 0; c < NCHUNK; c++) {
            if (c < NCHUNK - 1) asm volatile("cp.async.wait_group 1;" ::: "memory");
            else                asm volatile("cp.async.wait_group 0;" ::: "memory");
            __syncthreads();

            // issue next loads FIRST (stage stC-consumed-2-iters-ago is free)
            if (c + 2 < NCHUNK) load_chunk(c + 2, stL, false);

            const uint32_t asb = sbase + A_ST(stC);
            const uint32_t whb = sbase + W_HI_OFF + (uint32_t)(c * 4096);

            uint32_t ah0[4], ah1[4], al0[4], al1[4], bh0[4], bh1[4], bl0[4], bl1[4];
            ldsm4(ah0, asb + a_off0);
            ldsm4(ah1, asb + a_off1);
            ldsm4(bh0, whb + b_off0);
            ldsm4(bh1, whb + b_off1);
            ldsm4(al0, asb + 8192 + a_off0);
            ldsm4(al1, asb + 8192 + a_off1);
            ldsm4(bl0, whb + 65536 + b_off0);
            ldsm4(bl1, whb + 65536 + b_off1);

            // hi*hi
            mma_bf16(acc_h[0][0], ah0, bh0[0], bh0[1]);
            mma_bf16(acc_h[0][1], ah0, bh0[2], bh0[3]);
            mma_bf16(acc_h[0][2], ah0, bh1[0], bh1[1]);
            mma_bf16(acc_h[0][3], ah0, bh1[2], bh1[3]);
            mma_bf16(acc_h[1][0], ah1, bh0[0], bh0[1]);
            mma_bf16(acc_h[1][1], ah1, bh0[2], bh0[3]);
            mma_bf16(acc_h[1][2], ah1, bh1[0], bh1[1]);
            mma_bf16(acc_h[1][3], ah1, bh1[2], bh1[3]);
            // hi*lo
            mma_bf16(acc_m[0][0], ah0, bl0[0], bl0[1]);
            mma_bf16(acc_m[0][1], ah0, bl0[2], bl0[3]);
            mma_bf16(acc_m[0][2], ah0, bl1[0], bl1[1]);
            mma_bf16(acc_m[0][3], ah0, bl1[2], bl1[3]);
            mma_bf16(acc_m[1][0], ah1, bl0[0], bl0[1]);
            mma_bf16(acc_m[1][1], ah1, bl0[2], bl0[3]);
            mma_bf16(acc_m[1][2], ah1, bl1[0], bl1[1]);
            mma_bf16(acc_m[1][3], ah1, bl1[2], bl1[3]);
            // lo*hi
            mma_bf16(acc_m[0][0], al0, bh0[0], bh0[1]);
            mma_bf16(acc_m[0][1], al0, bh0[2], bh0[3]);
            mma_bf16(acc_m[0][2], al0, bh1[0], bh1[1]);
            mma_bf16(acc_m[0][3], al0, bh1[2], bh1[3]);
            mma_bf16(acc_m[1][0], al1, bh0[0], bh0[1]);
            mma_bf16(acc_m[1][1], al1, bh0[2], bh0[3]);
            mma_bf16(acc_m[1][2], al1, bh1[0], bh1[1]);
            mma_bf16(acc_m[1][3], al1, bh1[2], bh1[3]);

            stC = (stC == 2) ? 0 : stC + 1;
            stL = (stL == 2) ? 0 : stL + 1;
        }

        // ---- k-partial reduction + fused LSTM epilogue ----
        __syncthreads();                   // all ldsm done before ep overlays A
#pragma unroll
        for (int mt = 0; mt < 2; mt++) {
            const int r = mpos * 32 + mt * 16 + grp;
#pragma unroll
            for (int n8 = 0; n8 < 4; n8++) {
                const int ci = n8 * 8 + 2 * tig;
                myep[r * 36 + ci]           = acc_h[mt][n8][0] + acc_m[mt][n8][0];
                myep[r * 36 + ci + 1]       = acc_h[mt][n8][1] + acc_m[mt][n8][1];
                myep[(r + 8) * 36 + ci]     = acc_h[mt][n8][2] + acc_m[mt][n8][2];
                myep[(r + 8) * 36 + ci + 1] = acc_h[mt][n8][3] + acc_m[mt][n8][3];
            }
        }
        __syncthreads();

        {
            const int b = tid >> 2;
#pragma unroll
            for (int q = 0; q < 2; q++) {
                const int jj = (tid & 3) * 2 + q;
                float4 r0 = *(const float4*)&ep[b * 36 + jj * 4];
                float4 r1 = *(const float4*)&ep[2304 + b * 36 + jj * 4];
                float4 r2 = *(const float4*)&ep[4608 + b * 36 + jj * 4];
                float4 r3 = *(const float4*)&ep[6912 + b * 36 + jj * 4];
                float4 xv = *(const float4*)&xp_s[b * 32 + jj * 4];
                float gi = (r0.x + r1.x) + (r2.x + r3.x) + xv.x;
                float gf = (r0.y + r1.y) + (r2.y + r3.y) + xv.y;
                float ga = (r0.z + r1.z) + (r2.z + r3.z) + xv.z;
                float go = (r0.w + r1.w) + (r2.w + r3.w) + xv.w;
                float ig = sigmoidf_(gi);
                float fg = sigmoidf_(gf);
                float ag = tanhf(ga);
                float og = sigmoidf_(go);
                int j = cta * 8 + jj;
                float cnew = fg * cprev[b * HH + j] + ig * ag;
                float hnew = og * tanhf(cnew);
                g_c[b * HH + j]   = cnew;
                out_t[b * HH + j] = hnew;
                __nv_bfloat16 hi = __float2bfloat16(hnew);
                nhhi[b * HH + j] = hi;
                nhlo[b * HH + j] = __float2bfloat16(hnew - __bfloat162float(hi));
                if (t == TT - 1) {             // fused finalize: hy, cy
                    const size_t TBH = (size_t)TT * BB * HH;
                    out[TBH + b * HH + j]                   = hnew;
                    out[TBH + (size_t)BB * HH + b * HH + j] = cnew;
                }
            }
        }

        // ---- global barrier (tid0-only poll) ----
        if (t + 1 < TT) {
            __syncthreads();
            if (tid == 0) {
                __threadfence();
                atomicAdd(&g_bar, 1u);
                const unsigned target = (unsigned)NCTA * (unsigned)(t + 1);
                unsigned v;
                do {
                    asm volatile("ld.global.acquire.gpu.u32 %0, [%1];"
                                 : "=r"(v) : "l"(&g_bar));
                    if (v < target) __nanosleep(32);
                } while (v < target);
            }
            __syncthreads();
        }
    }
}

// ---------------------------------------------------------------------------
extern "C" void kernel_launch(void* const* d_in, const int* in_sizes, int n_in,
                              void* d_out, int out_size)
{
    const float* X    = (const float*)d_in[0];
    const float* hx   = (const float*)d_in[1];
    const float* cx   = (const float*)d_in[2];
    const float* w_ii = (const float*)d_in[3];
    const float* w_fi = (const float*)d_in[4];
    const float* w_ai = (const float*)d_in[5];
    const float* w_oi = (const float*)d_in[6];
    const float* w_ih = (const float*)d_in[7];
    const float* w_fh = (const float*)d_in[8];
    const float* w_ah = (const float*)d_in[9];
    const float* w_oh = (const float*)d_in[10];
    const float* b_i  = (const float*)d_in[11];
    const float* b_f  = (const float*)d_in[12];
    const float* b_a  = (const float*)d_in[13];
    const float* b_o  = (const float*)d_in[14];
    float* out = (float*)d_out;

    (void)in_sizes; (void)n_in; (void)out_size;

    cudaFuncSetAttribute(proj_hmma_kernel,
                         cudaFuncAttributeMaxDynamicSharedMemorySize, PSMEM);
    cudaFuncSetAttribute(lstm_persist_kernel,
                         cudaFuncAttributeMaxDynamicSharedMemorySize, SMEM_TOTAL);

    prep_wh<<<N4H, 128>>>(w_ih, w_fh, w_ah, w_oh);
    prep_wi<<<N4H, 128>>>(w_ii, w_fi, w_ai, w_oi);
    prep_bias<<<N4H / 256, 256>>>(b_i, b_f, b_a, b_o);
    prep_x<<<(int)((size_t)MTOT * II / 8 / 256), 256>>>(X);
    prep_h<<<(BB * HH) / 256, 256>>>(hx);

    dim3 pg(N4H / 128, MTOT / 128);
    proj_hmma_kernel<<<pg, 512, PSMEM>>>();

    lstm_persist_kernel<<<NCTA, 256, SMEM_TOTAL>>>(cx, out);
}